// round 14
// baseline (speedup 1.0000x reference)
#include <cuda_runtime.h>
#include <cuda_bf16.h>
#include <math.h>
#include <stdint.h>

#define Bb      64
#define T       512
#define D       2048
#define NBUF    16384
#define ROUNDS  10
#define GRIDB   128
#define PAD     72
#define SMEM_MM (1536 * PAD)   // bytes: 2 bufs x (A hi/lo 64*PAD + B hi/lo 128*PAD) bf16

// ---------------- scratch (static device globals; no allocation) -------------
// RULE: device symbols are ONLY referenced inside __global__ code, never passed
// as launch arguments (host symbol address + GB300 ATS = silent host aliasing).
__device__ float d_pooled[Bb * D];
__device__ float d_query[Bb * D];
__device__ float d_base[Bb * NBUF];
__device__ float d_AW[Bb * NBUF];
__device__ __align__(16) __nv_bfloat16 d_Ahi[Bb * NBUF];  // staged A operand (hi)
__device__ __align__(16) __nv_bfloat16 d_Alo[Bb * NBUF];  // staged A operand (lo)
__device__ float d_validf[NBUF];
__device__ float d_rs_part[GRIDB * Bb];   // [block][row] rowsum partials
__device__ float d_active[ROUNDS + 1];
__device__ float d_C1[Bb * D];
__device__ float d_part[4 * Bb * NBUF];   // 16.8 MB split-K partials
__device__ float d_wsum;
__device__ int   d_flag0;
__device__ int   d_flag1;
__device__ unsigned d_bar_cnt;
__device__ unsigned d_bar_gen;

// ---------------- mma helpers -------------------------------------------------
__device__ __forceinline__ void mma16816(float* c, const uint32_t* a,
                                         uint32_t b0, uint32_t b1) {
    asm volatile("mma.sync.aligned.m16n8k16.row.col.f32.bf16.bf16.f32 "
                 "{%0,%1,%2,%3}, {%4,%5,%6,%7}, {%8,%9}, {%0,%1,%2,%3};"
                 : "+f"(c[0]), "+f"(c[1]), "+f"(c[2]), "+f"(c[3])
                 : "r"(a[0]), "r"(a[1]), "r"(a[2]), "r"(a[3]), "r"(b0), "r"(b1));
}
__device__ __forceinline__ uint32_t pack2(__nv_bfloat16 a, __nv_bfloat16 b) {
    return ((uint32_t)__bfloat16_as_ushort(b) << 16) | __bfloat16_as_ushort(a);
}
__device__ __forceinline__ void split4(float4 v, uint2& H, uint2& L) {
    __nv_bfloat16 hx = __float2bfloat16(v.x), hy = __float2bfloat16(v.y);
    __nv_bfloat16 hz = __float2bfloat16(v.z), hw = __float2bfloat16(v.w);
    __nv_bfloat16 lx = __float2bfloat16(v.x - __bfloat162float(hx));
    __nv_bfloat16 ly = __float2bfloat16(v.y - __bfloat162float(hy));
    __nv_bfloat16 lz = __float2bfloat16(v.z - __bfloat162float(hz));
    __nv_bfloat16 lw = __float2bfloat16(v.w - __bfloat162float(hw));
    H.x = pack2(hx, hy); H.y = pack2(hz, hw);
    L.x = pack2(lx, ly); L.y = pack2(lz, lw);
}
__device__ __forceinline__ void splitw(float v, __nv_bfloat16& h, __nv_bfloat16& l) {
    h = __float2bfloat16(v);
    l = __float2bfloat16(v - __bfloat162float(h));
}
__device__ __forceinline__ double pack_dup(float a) {
    double r; asm("mov.b64 %0, {%1, %1};" : "=d"(r) : "f"(a)); return r;
}
__device__ __forceinline__ void fma2(double& acc, double a, double b) {
    asm("fma.rn.f32x2 %0, %1, %2, %0;" : "+d"(acc) : "d"(a), "d"(b));
}
__device__ __forceinline__ void unpack2(double v, float& lo, float& hi) {
    asm("mov.b64 {%0, %1}, %2;" : "=f"(lo), "=f"(hi) : "d"(v));
}

// ---------------- MODE table ---------------------------------------------------
// A comes from d_Ahi/d_Alo (pre-converted by the producer kernel of that stage).
// 0: d_part <- pooled @ Wq^T   Kslice=128, grid (16,16)
// 1: d_part <- query  @ keys^T Kslice=512, grid (128,4)
// 2: d_part <- AW @ values     Kslice=512, grid (16,32)  (row-contracted B)
// 3: d_part <- C1 @ Wc^T       Kslice=128, grid (16,16)
template<int MODE> struct MM {
    static const int TRANSB = (MODE == 2) ? 1 : 0;
    static const int LDA    = (MODE == 2) ? NBUF : D;
    static const int NTOT   = (MODE == 1) ? NBUF : D;
    static const int KSL    = (MODE == 0 || MODE == 3) ? 128 : 512;
};

// ---------------- split-precision bf16 mma GEMM, BK=64 double-buffered ---------
template<int MODE>
__global__ void __launch_bounds__(256) k_mm(const float* __restrict__ B, int ldb) {
    const int TRANSB = MM<MODE>::TRANSB;
    const int lda = MM<MODE>::LDA, Ntot = MM<MODE>::NTOT, Kslice = MM<MODE>::KSL;
    extern __shared__ __nv_bfloat16 sm_[];
    __nv_bfloat16* sAhi = sm_;                                   // [2][64*PAD]
    __nv_bfloat16* sAlo = sm_ + 2 * 64 * PAD;
    __nv_bfloat16* sBhi = sm_ + 4 * 64 * PAD;                    // [2][128*PAD]
    __nv_bfloat16* sBlo = sm_ + 4 * 64 * PAD + 2 * 128 * PAD;

    const int tid = threadIdx.x, lane = tid & 31, w = tid >> 5;
    const int wm = w >> 2, wn = w & 3;
    const int g = lane >> 2, t2 = (lane & 3) * 2;
    const int n0 = blockIdx.x * 128;
    const int kbase = blockIdx.y * Kslice;
    const int nct = Kslice >> 6;
    const int am = tid >> 2, ac = (tid & 3) * 16;   // A tile: 64 rows x 64 cols

    float acc[2][4][4];
#pragma unroll
    for (int f = 0; f < 2; f++)
#pragma unroll
        for (int q = 0; q < 4; q++)
#pragma unroll
            for (int i = 0; i < 4; i++) acc[f][q][i] = 0.f;

    uint4 rahi[2], ralo[2];
    float4 rb[8];
    auto loadT = [&](int c) {
        const int k0 = kbase + c * 64;
        rahi[0] = *(const uint4*)&d_Ahi[(size_t)am * lda + k0 + ac];
        rahi[1] = *(const uint4*)&d_Ahi[(size_t)am * lda + k0 + ac + 8];
        ralo[0] = *(const uint4*)&d_Alo[(size_t)am * lda + k0 + ac];
        ralo[1] = *(const uint4*)&d_Alo[(size_t)am * lda + k0 + ac + 8];
        if (!TRANSB) {
#pragma unroll
            for (int j = 0; j < 8; j++) {
                int idx = tid * 8 + j, r = idx >> 4, c4 = (idx & 15) * 4;
                rb[j] = *(const float4*)&B[(size_t)(n0 + r) * ldb + k0 + c4];
            }
        } else {
            int cc = tid & 127, rbse = (tid >> 7) * 32;
#pragma unroll
            for (int j = 0; j < 8; j++) {
                int rr = rbse + j * 4;
                rb[j].x = B[(size_t)(k0 + rr + 0) * ldb + n0 + cc];
                rb[j].y = B[(size_t)(k0 + rr + 1) * ldb + n0 + cc];
                rb[j].z = B[(size_t)(k0 + rr + 2) * ldb + n0 + cc];
                rb[j].w = B[(size_t)(k0 + rr + 3) * ldb + n0 + cc];
            }
        }
    };
    auto storeT = [&](int buf) {
        int abase = buf * 64 * PAD, bbase = buf * 128 * PAD;
        *(uint4*)&sAhi[abase + am * PAD + ac] = rahi[0];
        *(uint4*)&sAhi[abase + am * PAD + ac + 8] = rahi[1];
        *(uint4*)&sAlo[abase + am * PAD + ac] = ralo[0];
        *(uint4*)&sAlo[abase + am * PAD + ac + 8] = ralo[1];
        if (!TRANSB) {
#pragma unroll
            for (int j = 0; j < 8; j++) {
                int idx = tid * 8 + j, r = idx >> 4, c4 = (idx & 15) * 4;
                uint2 H, L; split4(rb[j], H, L);
                *(uint2*)&sBhi[bbase + r * PAD + c4] = H;
                *(uint2*)&sBlo[bbase + r * PAD + c4] = L;
            }
        } else {
            int cc = tid & 127, rbse = (tid >> 7) * 32;
#pragma unroll
            for (int j = 0; j < 8; j++) {
                int rr = rbse + j * 4;
                uint2 H, L; split4(rb[j], H, L);
                *(uint2*)&sBhi[bbase + cc * PAD + rr] = H;
                *(uint2*)&sBlo[bbase + cc * PAD + rr] = L;
            }
        }
    };

    loadT(0);
    storeT(0);
    __syncthreads();
    int buf = 0;
    for (int c = 0; c < nct; c++) {
        bool more = (c + 1 < nct);
        if (more) loadT(c + 1);
        const int abase = buf * 64 * PAD, bbase = buf * 128 * PAD;
#pragma unroll
        for (int ks = 0; ks < 64; ks += 16) {
            const int cA = ks + t2;
            uint32_t ahi[2][4], alo[2][4];
#pragma unroll
            for (int f = 0; f < 2; f++) {
                int rabs = abase + (wm * 32 + f * 16 + g) * PAD;
                ahi[f][0] = *(const uint32_t*)&sAhi[rabs + cA];
                ahi[f][1] = *(const uint32_t*)&sAhi[rabs + 8 * PAD + cA];
                ahi[f][2] = *(const uint32_t*)&sAhi[rabs + cA + 8];
                ahi[f][3] = *(const uint32_t*)&sAhi[rabs + 8 * PAD + cA + 8];
                alo[f][0] = *(const uint32_t*)&sAlo[rabs + cA];
                alo[f][1] = *(const uint32_t*)&sAlo[rabs + 8 * PAD + cA];
                alo[f][2] = *(const uint32_t*)&sAlo[rabs + cA + 8];
                alo[f][3] = *(const uint32_t*)&sAlo[rabs + 8 * PAD + cA + 8];
            }
#pragma unroll
            for (int nb = 0; nb < 4; nb++) {
                int ncb = bbase + (wn * 32 + nb * 8 + g) * PAD;
                uint32_t bh0 = *(const uint32_t*)&sBhi[ncb + cA];
                uint32_t bh1 = *(const uint32_t*)&sBhi[ncb + cA + 8];
                uint32_t bl0 = *(const uint32_t*)&sBlo[ncb + cA];
                uint32_t bl1 = *(const uint32_t*)&sBlo[ncb + cA + 8];
#pragma unroll
                for (int f = 0; f < 2; f++) {
                    mma16816(acc[f][nb], ahi[f], bh0, bh1);
                    mma16816(acc[f][nb], ahi[f], bl0, bl1);
                    mma16816(acc[f][nb], alo[f], bh0, bh1);
                }
            }
        }
        if (more) storeT(buf ^ 1);
        __syncthreads();
        buf ^= 1;
    }

    float* Cp = d_part + (size_t)blockIdx.y * 64 * Ntot;
    int r0 = wm * 32 + g;
#pragma unroll
    for (int f = 0; f < 2; f++)
#pragma unroll
        for (int nb = 0; nb < 4; nb++) {
            int rr = r0 + f * 16;
            int col = n0 + wn * 32 + nb * 8 + t2;
            *(float2*)&Cp[(size_t)rr * Ntot + col] =
                make_float2(acc[f][nb][0], acc[f][nb][1]);
            *(float2*)&Cp[(size_t)(rr + 8) * Ntot + col] =
                make_float2(acc[f][nb][2], acc[f][nb][3]);
        }
}

// ---------------- fp32 sample check ------------------------------------------
template<int CHK>
__global__ void k_check(const float* __restrict__ B, int ldb,
                        const float* __restrict__ bias) {
    const float* __restrict__ A   = (CHK == 0) ? d_pooled : d_AW;
    const float* __restrict__ Cc  = (CHK == 0) ? d_query : d_C1;
    const int lda = (CHK == 0) ? D : NBUF;
    const int K   = (CHK == 0) ? D : NBUF;
    int gw = (blockIdx.x * blockDim.x + threadIdx.x) >> 5;
    int lane = threadIdx.x & 31;
    int row = (gw * 37) & 63;
    int col = (int)((gw * 2654435761u) % (unsigned)D);
    float s0 = 0.f, s1 = 0.f, s2 = 0.f, s3 = 0.f;
    if (CHK == 0) {
        for (int k = lane * 4; k < K; k += 128) {
            s0 += A[(size_t)row * lda + k + 0] * B[(size_t)col * ldb + k + 0];
            s1 += A[(size_t)row * lda + k + 1] * B[(size_t)col * ldb + k + 1];
            s2 += A[(size_t)row * lda + k + 2] * B[(size_t)col * ldb + k + 2];
            s3 += A[(size_t)row * lda + k + 3] * B[(size_t)col * ldb + k + 3];
        }
    } else {
        for (int k = lane * 4; k < K; k += 128) {
            s0 += A[(size_t)row * lda + k + 0] * B[(size_t)(k + 0) * ldb + col];
            s1 += A[(size_t)row * lda + k + 1] * B[(size_t)(k + 1) * ldb + col];
            s2 += A[(size_t)row * lda + k + 2] * B[(size_t)(k + 2) * ldb + col];
            s3 += A[(size_t)row * lda + k + 3] * B[(size_t)(k + 3) * ldb + col];
        }
    }
    float s = (s0 + s1) + (s2 + s3);
#pragma unroll
    for (int o = 16; o; o >>= 1) s += __shfl_xor_sync(0xFFFFFFFFu, s, o);
    if (lane == 0) {
        float ref = s + (bias ? bias[col] : 0.f);
        float got = Cc[(size_t)row * D + col];
        float tol = 0.02f * fabsf(ref) + 1e-3f;
        if (!(fabsf(got - ref) <= tol)) {
            if (CHK == 0) atomicExch(&d_flag0, 1);
            else          atomicExch(&d_flag1, 1);
        }
    }
}

// ---------------- f32x2 fallback GEMM (flag-gated) ----------------------------
template<int FM>
__global__ void __launch_bounds__(256) k_fp(const float* __restrict__ B, int ldb,
                                            const float* __restrict__ bias,
                                            float* __restrict__ outp) {
    if (((FM == 2) ? d_flag1 : d_flag0) == 0) return;
    const float* __restrict__ A = (FM == 0) ? d_pooled : (FM == 1) ? d_query
                                 : (FM == 2) ? d_AW : d_C1;
    float* __restrict__ Cout = (FM == 0) ? d_query : (FM == 1) ? d_base
                               : (FM == 2) ? d_C1 : outp;
    const int lda  = (FM == 2) ? NBUF : D;
    const int K    = (FM == 2) ? NBUF : D;
    const int Ntot = (FM == 1) ? NBUF : D;
    const int TRANSB = (FM == 2) ? 1 : 0;
    const float scale = (FM == 1) ? 0.022097086912079608f : 1.0f;

    __shared__ float As[32][64];
    __shared__ float Bs[32][128];
    const int tid = threadIdx.x, tx = tid & 15, ty = tid >> 4;
    const int n0 = blockIdx.x * 128;
    double acc[4][4];
#pragma unroll
    for (int i = 0; i < 4; i++)
#pragma unroll
        for (int j = 0; j < 4; j++) acc[i][j] = 0.0;

    for (int k0 = 0; k0 < K; k0 += 32) {
#pragma unroll
        for (int j = 0; j < 2; j++) {
            int idx = tid * 2 + j, m = idx >> 3, c4 = idx & 7;
            float4 v = *(const float4*)&A[(size_t)m * lda + k0 + c4 * 4];
            As[c4 * 4 + 0][m] = v.x; As[c4 * 4 + 1][m] = v.y;
            As[c4 * 4 + 2][m] = v.z; As[c4 * 4 + 3][m] = v.w;
        }
        if (!TRANSB) {
#pragma unroll
            for (int j = 0; j < 4; j++) {
                int idx = tid * 4 + j, n = idx >> 3, c4 = idx & 7;
                float4 v = *(const float4*)&B[(size_t)(n0 + n) * ldb + k0 + c4 * 4];
                Bs[c4 * 4 + 0][n] = v.x; Bs[c4 * 4 + 1][n] = v.y;
                Bs[c4 * 4 + 2][n] = v.z; Bs[c4 * 4 + 3][n] = v.w;
            }
        } else {
#pragma unroll
            for (int j = 0; j < 4; j++) {
                int idx = tid * 4 + j, kk = idx >> 5, n4 = idx & 31;
                *(float4*)&Bs[kk][n4 * 4] =
                    *(const float4*)&B[(size_t)(k0 + kk) * ldb + n0 + n4 * 4];
            }
        }
        __syncthreads();
#pragma unroll 8
        for (int kk = 0; kk < 32; kk++) {
            float4 av = *(const float4*)&As[kk][ty * 4];
            double2 b01 = *(const double2*)&Bs[kk][tx * 8];
            double2 b23 = *(const double2*)&Bs[kk][tx * 8 + 4];
            double a0 = pack_dup(av.x), a1 = pack_dup(av.y);
            double a2 = pack_dup(av.z), a3 = pack_dup(av.w);
            fma2(acc[0][0], a0, b01.x); fma2(acc[0][1], a0, b01.y);
            fma2(acc[0][2], a0, b23.x); fma2(acc[0][3], a0, b23.y);
            fma2(acc[1][0], a1, b01.x); fma2(acc[1][1], a1, b01.y);
            fma2(acc[1][2], a1, b23.x); fma2(acc[1][3], a1, b23.y);
            fma2(acc[2][0], a2, b01.x); fma2(acc[2][1], a2, b01.y);
            fma2(acc[2][2], a2, b23.x); fma2(acc[2][3], a2, b23.y);
            fma2(acc[3][0], a3, b01.x); fma2(acc[3][1], a3, b01.y);
            fma2(acc[3][2], a3, b23.x); fma2(acc[3][3], a3, b23.y);
        }
        __syncthreads();
    }
    float ws = d_wsum;
#pragma unroll
    for (int i = 0; i < 4; i++) {
        int row = ty * 4 + i;
        float o[8];
        unpack2(acc[i][0], o[0], o[1]); unpack2(acc[i][1], o[2], o[3]);
        unpack2(acc[i][2], o[4], o[5]); unpack2(acc[i][3], o[6], o[7]);
#pragma unroll
        for (int j = 0; j < 8; j++) {
            int col = n0 + tx * 8 + j;
            float c = o[j] * scale;
            if (FM == 3)       c = (ws > 0.f) ? c / fmaxf(ws, 1e-8f) + bias[col] : 0.f;
            else if (FM == 0)  c += bias[col];
            Cout[(size_t)row * Ntot + col] = c;
            if (FM == 0 || FM == 2) {  // refresh bf16 staging for next mma stage
                __nv_bfloat16 h, l; splitw(c, h, l);
                d_Ahi[(size_t)row * Ntot + col] = h;
                d_Alo[(size_t)row * Ntot + col] = l;
            }
        }
    }
}

// ---------------- valid_mask dtype detection + init ---------------------------
__global__ void k_detect(const void* vm) {
    __shared__ int mode;
    if (threadIdx.x == 0) {
        const float* fp = (const float*)vm;
        const int*   ip = (const int*)vm;
        bool isF = true, isI = true;
        for (int k = 0; k < 64; k++) {
            float f = fp[k];
            if (!(f == 0.0f || f == 1.0f)) isF = false;
            int v = ip[k];
            if (!(v == 0 || v == 1)) isI = false;
        }
        mode = isF ? 2 : (isI ? 1 : 0);
    }
    __syncthreads();
    int m = mode;
    const unsigned char* cp = (const unsigned char*)vm;
    const int*   ip = (const int*)vm;
    const float* fp = (const float*)vm;
    for (int n = threadIdx.x; n < NBUF; n += blockDim.x) {
        float v;
        if (m == 2)      v = (fp[n] != 0.0f) ? 1.f : 0.f;
        else if (m == 1) v = (ip[n] != 0)    ? 1.f : 0.f;
        else             v = (cp[n] != 0)    ? 1.f : 0.f;
        d_validf[n] = v;
    }
    if (threadIdx.x <= ROUNDS) d_active[threadIdx.x] = 0.f;
    if (threadIdx.x == 0) { d_wsum = 0.f; d_flag0 = 0; d_flag1 = 0; }
}

// ---------------- masked mean pool (writes fp32 + bf16 hi/lo) ------------------
__global__ void __launch_bounds__(256) k_pool(const float* __restrict__ qs,
                                              const float* __restrict__ mask) {
    int b = blockIdx.y;
    int d = blockIdx.x * 256 + threadIdx.x;
    __shared__ float sm[T];
    __shared__ float red[256];
    for (int t = threadIdx.x; t < T; t += 256) sm[t] = mask[b * T + t];
    __syncthreads();
    red[threadIdx.x] = sm[threadIdx.x] + sm[threadIdx.x + 256];
    __syncthreads();
    for (int off = 128; off > 0; off >>= 1) {
        if (threadIdx.x < off) red[threadIdx.x] += red[threadIdx.x + off];
        __syncthreads();
    }
    float msum = red[0];
    const float* base = qs + ((size_t)b * T) * D + d;
    float a0 = 0, a1 = 0, a2 = 0, a3 = 0;
#pragma unroll 2
    for (int t = 0; t < T; t += 8) {
        a0 += base[(size_t)(t + 0) * D] * sm[t + 0];
        a1 += base[(size_t)(t + 1) * D] * sm[t + 1];
        a2 += base[(size_t)(t + 2) * D] * sm[t + 2];
        a3 += base[(size_t)(t + 3) * D] * sm[t + 3];
        a0 += base[(size_t)(t + 4) * D] * sm[t + 4];
        a1 += base[(size_t)(t + 5) * D] * sm[t + 5];
        a2 += base[(size_t)(t + 6) * D] * sm[t + 6];
        a3 += base[(size_t)(t + 7) * D] * sm[t + 7];
    }
    float v = (a0 + a1 + a2 + a3) / (msum + 1e-8f);
    int idx = b * D + d;
    d_pooled[idx] = v;
    __nv_bfloat16 h, l; splitw(v, h, l);
    d_Ahi[idx] = h; d_Alo[idx] = l;
}

// ---------------- split-K reduces (producers also stage bf16) ------------------
__global__ void k_reduce_q(const float* __restrict__ bq) {
    int idx = blockIdx.x * 256 + threadIdx.x;
    if (idx >= Bb * D) return;
    float s = 0.f;
#pragma unroll
    for (int kz = 0; kz < 16; kz++) s += d_part[(size_t)kz * Bb * D + idx];
    float v = s + bq[idx & (D - 1)];
    d_query[idx] = v;
    __nv_bfloat16 h, l; splitw(v, h, l);
    d_Ahi[idx] = h; d_Alo[idx] = l;
}

__global__ void k_reduce_base() {
    int idx = blockIdx.x * 256 + threadIdx.x;
    float s = 0.f;
#pragma unroll
    for (int kz = 0; kz < 4; kz++) s += d_part[(size_t)kz * Bb * NBUF + idx];
    d_base[idx] = s * 0.022097086912079608f;
}

__global__ void k_reduce_c1() {
    int idx = blockIdx.x * 256 + threadIdx.x;
    if (idx >= Bb * D) return;
    float s = 0.f;
#pragma unroll
    for (int kz = 0; kz < 32; kz++) s += d_part[(size_t)kz * Bb * D + idx];
    d_C1[idx] = s;
    __nv_bfloat16 h, l; splitw(s, h, l);
    d_Ahi[idx] = h; d_Alo[idx] = l;
}

__global__ void k_reduce_out(const float* __restrict__ bc, float* __restrict__ out) {
    int idx = blockIdx.x * 256 + threadIdx.x;
    if (idx >= Bb * D) return;
    float ws = d_wsum;
    if (ws > 0.f) {
        float s = 0.f;
#pragma unroll
        for (int kz = 0; kz < 16; kz++) s += d_part[(size_t)kz * Bb * D + idx];
        out[idx] = s / fmaxf(ws, 1e-8f) + bc[idx & (D - 1)];
    } else {
        out[idx] = 0.f;
    }
}

// ---------------- persistent round-loop kernel (column-resident) ---------------
__device__ __forceinline__ void gridbar() {
    __syncthreads();
    if (threadIdx.x == 0) {
        __threadfence();
        unsigned g = atomicAdd(&d_bar_gen, 0u);
        if (atomicAdd(&d_bar_cnt, 1u) == GRIDB - 1u) {
            d_bar_cnt = 0u;
            __threadfence();
            atomicAdd(&d_bar_gen, 1u);
        } else {
            while (atomicAdd(&d_bar_gen, 0u) == g) { }
        }
        __threadfence();
    }
    __syncthreads();
}

__global__ void __launch_bounds__(256) k_rounds(const float* __restrict__ prio,
                                                const float* __restrict__ ages) {
    const int tid = threadIdx.x, blk = blockIdx.x;
    const int lane = tid & 31, wrp = tid >> 5;
    const int half = wrp >> 2;            // 0: rows 0..31, 1: rows 32..63
    const int col = blk * 128 + (tid & 127);
    const int blo = half * 32;
    __shared__ float spart[8][32];
    __shared__ float red[256];
    __shared__ float invs[64];
    const float DK = -0.105360515657826301f;  // ln(0.9)

    float wage = ages[col];
    float p    = prio[col];
    float vf   = d_validf[col];
    float gg, act;
    {
        float eff = p * __expf(wage * DK);
        act = vf / (1.f + __expf((0.5f - eff) * 10.f));
        gg = act * eff;
    }
    float aw_acc[32], e[32];
#pragma unroll
    for (int j = 0; j < 32; j++) aw_acc[j] = 0.f;

    // active(0): one thread per column contributes
    red[tid] = (tid < 128) ? act : 0.f; __syncthreads();
    for (int off = 128; off; off >>= 1) {
        if (tid < off) red[tid] += red[tid + off];
        __syncthreads();
    }
    if (tid == 0) atomicAdd(&d_active[0], red[0]);
    gridbar();

    float wsum = 0.f, rw = 1.f;
    for (int r = 0; r < ROUNDS; r++) {
        if (__ldcg(&d_active[r]) < 0.5f) break;
        wsum += rw;

        // ---- Phase 1: e in regs; per-warp row partials via shfl butterfly
#pragma unroll 8
        for (int j = 0; j < 32; j++)
            e[j] = vf * __expf(__ldg(&d_base[(size_t)(blo + j) * NBUF + col]) * gg);
#pragma unroll
        for (int j = 0; j < 32; j++) {
            float v = e[j];
#pragma unroll
            for (int off = 16; off; off >>= 1)
                v += __shfl_xor_sync(0xFFFFFFFFu, v, off);
            if (lane == j) spart[wrp][j] = v;
        }
        __syncthreads();
        if (tid < 64) {
            int hb = (tid >> 5) * 4, j = tid & 31;
            float t = spart[hb + 0][j] + spart[hb + 1][j]
                    + spart[hb + 2][j] + spart[hb + 3][j];
            __stcg(&d_rs_part[blk * Bb + tid], t);
        }
        gridbar();

        // ---- Phase 2: global rowsums -> invs
        {
            int rrow = tid & 63, grp = tid >> 6;
            float s = 0.f;
#pragma unroll 8
            for (int bi = 0; bi < 32; bi++)
                s += __ldcg(&d_rs_part[(size_t)(grp * 32 + bi) * Bb + rrow]);
            red[tid] = s; __syncthreads();
            if (tid < 64)
                invs[tid] = 1.f / (red[tid] + red[tid + 64] + red[tid + 128] + red[tid + 192]);
            __syncthreads();
        }
        // ---- aw accumulate + column sums
        float cs = 0.f;
#pragma unroll
        for (int j = 0; j < 32; j++) {
            float a = e[j] * invs[blo + j];
            aw_acc[j] += rw * a;
            cs += a;
        }
        __syncthreads();
        red[tid] = cs; __syncthreads();
        float cfull = red[tid & 127] + red[(tid & 127) + 128];
        wage += cfull * (1.f / 64.f);
        {
            float eff = p * __expf(wage * DK);
            act = vf / (1.f + __expf((0.5f - eff) * 10.f));
            gg = act * eff;
        }
        __syncthreads();
        red[tid] = (tid < 128) ? act : 0.f; __syncthreads();
        for (int off = 128; off; off >>= 1) {
            if (tid < off) red[tid] += red[tid + off];
            __syncthreads();
        }
        if (tid == 0) atomicAdd(&d_active[r + 1], red[0]);
        gridbar();
        rw *= 0.9f;
    }
    // final AW store: fp32 (for check/fallback) + bf16 hi/lo staging for mm2
#pragma unroll 8
    for (int j = 0; j < 32; j++) {
        size_t idx = (size_t)(blo + j) * NBUF + col;
        float v = aw_acc[j];
        d_AW[idx] = v;
        __nv_bfloat16 h, l; splitw(v, h, l);
        d_Ahi[idx] = h; d_Alo[idx] = l;
    }
    if (blk == 0 && tid == 0) d_wsum = wsum;
}

// ---------------- launch ------------------------------------------------------
extern "C" void kernel_launch(void* const* d_in, const int* in_sizes, int n_in,
                              void* d_out, int out_size) {
    const float* qs     = (const float*)d_in[0];
    const float* amask  = (const float*)d_in[1];
    const float* keys   = (const float*)d_in[2];
    const float* values = (const float*)d_in[3];
    const float* prio   = (const float*)d_in[4];
    const float* ages   = (const float*)d_in[5];
    const void*  vmask  = d_in[6];
    const float* Wq     = (const float*)d_in[7];
    const float* bq     = (const float*)d_in[8];
    const float* Wc     = (const float*)d_in[9];
    const float* bc     = (const float*)d_in[10];
    float* out = (float*)d_out;

    cudaFuncSetAttribute(k_mm<0>, cudaFuncAttributeMaxDynamicSharedMemorySize, SMEM_MM);
    cudaFuncSetAttribute(k_mm<1>, cudaFuncAttributeMaxDynamicSharedMemorySize, SMEM_MM);
    cudaFuncSetAttribute(k_mm<2>, cudaFuncAttributeMaxDynamicSharedMemorySize, SMEM_MM);
    cudaFuncSetAttribute(k_mm<3>, cudaFuncAttributeMaxDynamicSharedMemorySize, SMEM_MM);

    k_detect<<<1, 256>>>(vmask);
    k_pool<<<dim3(8, 64), 256>>>(qs, amask);

    // query = pooled @ Wq^T + bq  (mma split-K=16; checked; f32x2 fallback)
    k_mm<0><<<dim3(16, 16), 256, SMEM_MM>>>(Wq, D);
    k_reduce_q<<<(Bb * D + 255) / 256, 256>>>(bq);
    k_check<0><<<8, 256>>>(Wq, D, bq);
    k_fp<0><<<16, 256>>>(Wq, D, bq, (float*)0);

    // base = query @ keys^T * SC  (mma split-K=4; gated by flag0)
    k_mm<1><<<dim3(128, 4), 256, SMEM_MM>>>(keys, D);
    k_reduce_base<<<(Bb * NBUF) / 256, 256>>>();
    k_fp<1><<<128, 256>>>(keys, D, (const float*)0, (float*)0);

    k_rounds<<<GRIDB, 256>>>(prio, ages);

    // C1 = AW @ values  (mma split-K=32; checked; fallback)
    k_mm<2><<<dim3(16, 32), 256, SMEM_MM>>>(values, D);
    k_reduce_c1<<<(Bb * D + 255) / 256, 256>>>();
    k_check<1><<<1, 256>>>(values, D, (const float*)0);
    k_fp<2><<<16, 256>>>(values, D, (const float*)0, (float*)0);

    // out = (C1 @ Wc^T)/wsum + bc
    k_mm<3><<<dim3(16, 16), 256, SMEM_MM>>>(Wc, D);
    k_reduce_out<<<(Bb * D + 255) / 256, 256>>>(bc, out);
    k_fp<3><<<16, 256>>>(Wc, D, bc, out);
}

// round 15
// speedup vs baseline: 1.0988x; 1.0988x over previous
#include <cuda_runtime.h>
#include <cuda_bf16.h>
#include <math.h>
#include <stdint.h>

#define Bb      64
#define T       512
#define D       2048
#define NBUF    16384
#define ROUNDS  10
#define GRIDB   128
#define PAD     40
#define SMEM_MM (1536 * PAD)   // bytes: 2 bufs x (A hi/lo 64*PAD + B hi/lo 128*PAD) bf16

// ---------------- scratch (static device globals; no allocation) -------------
// RULE: device symbols are ONLY referenced inside __global__ code, never passed
// as launch arguments (host symbol address + GB300 ATS = silent host aliasing).
__device__ float d_pooled[Bb * D];
__device__ float d_query[Bb * D];
__device__ float d_base[Bb * NBUF];
__device__ float d_AW[Bb * NBUF];
__device__ __align__(16) __nv_bfloat16 d_Ahi[Bb * NBUF];  // staged A operand (hi)
__device__ __align__(16) __nv_bfloat16 d_Alo[Bb * NBUF];  // staged A operand (lo)
__device__ float d_validf[NBUF];
__device__ float d_rs_part[GRIDB * Bb];   // [block][row] rowsum partials
__device__ float d_active[ROUNDS + 1];
__device__ float d_C1[Bb * D];
__device__ float d_part[4 * Bb * NBUF];   // 16.8 MB split-K partials
__device__ float d_wsum;
__device__ int   d_flag0;
__device__ int   d_flag1;
__device__ unsigned d_bar_cnt;
__device__ unsigned d_bar_gen;

// ---------------- helpers -------------------------------------------------
__device__ __forceinline__ uint32_t smem_u32(const void* p) {
    uint32_t a;
    asm("{ .reg .u64 t; cvta.to.shared.u64 t, %1; cvt.u32.u64 %0, t; }"
        : "=r"(a) : "l"(p));
    return a;
}
#define CPA16(dst, src) \
    asm volatile("cp.async.ca.shared.global [%0], [%1], 16;" :: "r"(dst), "l"(src))
#define CPA_COMMIT() asm volatile("cp.async.commit_group;" ::: "memory")
#define CPA_WAIT0()  asm volatile("cp.async.wait_group 0;" ::: "memory")

__device__ __forceinline__ void mma16816(float* c, const uint32_t* a,
                                         uint32_t b0, uint32_t b1) {
    asm volatile("mma.sync.aligned.m16n8k16.row.col.f32.bf16.bf16.f32 "
                 "{%0,%1,%2,%3}, {%4,%5,%6,%7}, {%8,%9}, {%0,%1,%2,%3};"
                 : "+f"(c[0]), "+f"(c[1]), "+f"(c[2]), "+f"(c[3])
                 : "r"(a[0]), "r"(a[1]), "r"(a[2]), "r"(a[3]), "r"(b0), "r"(b1));
}
__device__ __forceinline__ uint32_t pack2(__nv_bfloat16 a, __nv_bfloat16 b) {
    return ((uint32_t)__bfloat16_as_ushort(b) << 16) | __bfloat16_as_ushort(a);
}
__device__ __forceinline__ void split4(float4 v, uint2& H, uint2& L) {
    __nv_bfloat16 hx = __float2bfloat16(v.x), hy = __float2bfloat16(v.y);
    __nv_bfloat16 hz = __float2bfloat16(v.z), hw = __float2bfloat16(v.w);
    __nv_bfloat16 lx = __float2bfloat16(v.x - __bfloat162float(hx));
    __nv_bfloat16 ly = __float2bfloat16(v.y - __bfloat162float(hy));
    __nv_bfloat16 lz = __float2bfloat16(v.z - __bfloat162float(hz));
    __nv_bfloat16 lw = __float2bfloat16(v.w - __bfloat162float(hw));
    H.x = pack2(hx, hy); H.y = pack2(hz, hw);
    L.x = pack2(lx, ly); L.y = pack2(lz, lw);
}
__device__ __forceinline__ void splitw(float v, __nv_bfloat16& h, __nv_bfloat16& l) {
    h = __float2bfloat16(v);
    l = __float2bfloat16(v - __bfloat162float(h));
}
__device__ __forceinline__ double pack_dup(float a) {
    double r; asm("mov.b64 %0, {%1, %1};" : "=d"(r) : "f"(a)); return r;
}
__device__ __forceinline__ void fma2(double& acc, double a, double b) {
    asm("fma.rn.f32x2 %0, %1, %2, %0;" : "+d"(acc) : "d"(a), "d"(b));
}
__device__ __forceinline__ void unpack2(double v, float& lo, float& hi) {
    asm("mov.b64 {%0, %1}, %2;" : "=f"(lo), "=f"(hi) : "d"(v));
}

// ---------------- MODE table ---------------------------------------------------
// A comes from d_Ahi/d_Alo (pre-converted by the producer kernel of that stage).
// 0: d_part <- pooled @ Wq^T   Kslice=128, grid (16,16)
// 1: d_part <- query  @ keys^T Kslice=512, grid (128,4)
// 2: d_part <- AW @ values     Kslice=512, grid (16,32)  (row-contracted B)
// 3: d_part <- C1 @ Wc^T       Kslice=128, grid (16,16)
template<int MODE> struct MM {
    static const int TRANSB = (MODE == 2) ? 1 : 0;
    static const int LDA    = (MODE == 2) ? NBUF : D;
    static const int NTOT   = (MODE == 1) ? NBUF : D;
    static const int KSL    = (MODE == 0 || MODE == 3) ? 128 : 512;
};

// ---------------- split-precision bf16 mma GEMM, cp.async A, BK=32 -------------
template<int MODE>
__global__ void __launch_bounds__(256) k_mm(const float* __restrict__ B, int ldb) {
    const int TRANSB = MM<MODE>::TRANSB;
    const int lda = MM<MODE>::LDA, Ntot = MM<MODE>::NTOT, Kslice = MM<MODE>::KSL;
    extern __shared__ __nv_bfloat16 sm_[];
    __nv_bfloat16* sAhi = sm_;                                   // [2][64*PAD]
    __nv_bfloat16* sAlo = sm_ + 2 * 64 * PAD;
    __nv_bfloat16* sBhi = sm_ + 4 * 64 * PAD;                    // [2][128*PAD]
    __nv_bfloat16* sBlo = sm_ + 4 * 64 * PAD + 2 * 128 * PAD;

    const int tid = threadIdx.x, lane = tid & 31, w = tid >> 5;
    const int wm = w >> 2, wn = w & 3;
    const int g = lane >> 2, t2 = (lane & 3) * 2;
    const int n0 = blockIdx.x * 128;
    const int kbase = blockIdx.y * Kslice;
    const int nct = Kslice >> 5;
    const int am = tid >> 2, ac8 = (tid & 3) * 8;   // A tile: 64 rows x 32 cols / 8

    float acc[2][4][4];
#pragma unroll
    for (int f = 0; f < 2; f++)
#pragma unroll
        for (int q = 0; q < 4; q++)
#pragma unroll
            for (int i = 0; i < 4; i++) acc[f][q][i] = 0.f;

    float4 rb[4];
    // async copy of A (hi+lo) for chunk c into buffer buf
    auto loadA = [&](int c, int buf) {
        const int k0 = kbase + c * 32;
        int abase = buf * 64 * PAD;
        uint32_t dh = smem_u32(&sAhi[abase + am * PAD + ac8]);
        uint32_t dl = smem_u32(&sAlo[abase + am * PAD + ac8]);
        CPA16(dh, &d_Ahi[(size_t)am * lda + k0 + ac8]);
        CPA16(dl, &d_Alo[(size_t)am * lda + k0 + ac8]);
        CPA_COMMIT();
    };
    auto loadB = [&](int c) {
        const int k0 = kbase + c * 32;
        if (!TRANSB) {
#pragma unroll
            for (int j = 0; j < 4; j++) {
                int idx = tid * 4 + j, r = idx >> 3, c4 = (idx & 7) * 4;
                rb[j] = *(const float4*)&B[(size_t)(n0 + r) * ldb + k0 + c4];
            }
        } else {
            int cc = tid & 127, rbse = (tid >> 7) * 4;
#pragma unroll
            for (int j = 0; j < 4; j++) {
                int rr = rbse + j * 8;
                rb[j].x = B[(size_t)(k0 + rr + 0) * ldb + n0 + cc];
                rb[j].y = B[(size_t)(k0 + rr + 1) * ldb + n0 + cc];
                rb[j].z = B[(size_t)(k0 + rr + 2) * ldb + n0 + cc];
                rb[j].w = B[(size_t)(k0 + rr + 3) * ldb + n0 + cc];
            }
        }
    };
    auto storeB = [&](int buf) {
        int bbase = buf * 128 * PAD;
        if (!TRANSB) {
#pragma unroll
            for (int j = 0; j < 4; j++) {
                int idx = tid * 4 + j, r = idx >> 3, c4 = (idx & 7) * 4;
                uint2 H, L; split4(rb[j], H, L);
                *(uint2*)&sBhi[bbase + r * PAD + c4] = H;
                *(uint2*)&sBlo[bbase + r * PAD + c4] = L;
            }
        } else {
            int cc = tid & 127, rbse = (tid >> 7) * 4;
#pragma unroll
            for (int j = 0; j < 4; j++) {
                int rr = rbse + j * 8;
                uint2 H, L; split4(rb[j], H, L);
                *(uint2*)&sBhi[bbase + cc * PAD + rr] = H;
                *(uint2*)&sBlo[bbase + cc * PAD + rr] = L;
            }
        }
    };

    loadA(0, 0);
    loadB(0);
    storeB(0);
    CPA_WAIT0();
    __syncthreads();
    int buf = 0;
    for (int c = 0; c < nct; c++) {
        bool more = (c + 1 < nct);
        if (more) { loadA(c + 1, buf ^ 1); loadB(c + 1); }
        const int abase = buf * 64 * PAD, bbase = buf * 128 * PAD;
#pragma unroll
        for (int ks = 0; ks < 32; ks += 16) {
            const int cA = ks + t2;
            uint32_t ahi[2][4], alo[2][4];
#pragma unroll
            for (int f = 0; f < 2; f++) {
                int rabs = abase + (wm * 32 + f * 16 + g) * PAD;
                ahi[f][0] = *(const uint32_t*)&sAhi[rabs + cA];
                ahi[f][1] = *(const uint32_t*)&sAhi[rabs + 8 * PAD + cA];
                ahi[f][2] = *(const uint32_t*)&sAhi[rabs + cA + 8];
                ahi[f][3] = *(const uint32_t*)&sAhi[rabs + 8 * PAD + cA + 8];
                alo[f][0] = *(const uint32_t*)&sAlo[rabs + cA];
                alo[f][1] = *(const uint32_t*)&sAlo[rabs + 8 * PAD + cA];
                alo[f][2] = *(const uint32_t*)&sAlo[rabs + cA + 8];
                alo[f][3] = *(const uint32_t*)&sAlo[rabs + 8 * PAD + cA + 8];
            }
#pragma unroll
            for (int nb = 0; nb < 4; nb++) {
                int ncb = bbase + (wn * 32 + nb * 8 + g) * PAD;
                uint32_t bh0 = *(const uint32_t*)&sBhi[ncb + cA];
                uint32_t bh1 = *(const uint32_t*)&sBhi[ncb + cA + 8];
                uint32_t bl0 = *(const uint32_t*)&sBlo[ncb + cA];
                uint32_t bl1 = *(const uint32_t*)&sBlo[ncb + cA + 8];
#pragma unroll
                for (int f = 0; f < 2; f++) {
                    mma16816(acc[f][nb], ahi[f], bh0, bh1);
                    mma16816(acc[f][nb], ahi[f], bl0, bl1);
                    mma16816(acc[f][nb], alo[f], bh0, bh1);
                }
            }
        }
        if (more) { storeB(buf ^ 1); CPA_WAIT0(); }
        __syncthreads();
        buf ^= 1;
    }

    float* Cp = d_part + (size_t)blockIdx.y * 64 * Ntot;
    int r0 = wm * 32 + g;
#pragma unroll
    for (int f = 0; f < 2; f++)
#pragma unroll
        for (int nb = 0; nb < 4; nb++) {
            int rr = r0 + f * 16;
            int col = n0 + wn * 32 + nb * 8 + t2;
            *(float2*)&Cp[(size_t)rr * Ntot + col] =
                make_float2(acc[f][nb][0], acc[f][nb][1]);
            *(float2*)&Cp[(size_t)(rr + 8) * Ntot + col] =
                make_float2(acc[f][nb][2], acc[f][nb][3]);
        }
}

// ---------------- fp32 sample check ------------------------------------------
template<int CHK>
__global__ void k_check(const float* __restrict__ B, int ldb,
                        const float* __restrict__ bias) {
    const float* __restrict__ A   = (CHK == 0) ? d_pooled : d_AW;
    const float* __restrict__ Cc  = (CHK == 0) ? d_query : d_C1;
    const int lda = (CHK == 0) ? D : NBUF;
    const int K   = (CHK == 0) ? D : NBUF;
    int gw = (blockIdx.x * blockDim.x + threadIdx.x) >> 5;
    int lane = threadIdx.x & 31;
    int row = (gw * 37) & 63;
    int col = (int)((gw * 2654435761u) % (unsigned)D);
    float s0 = 0.f, s1 = 0.f, s2 = 0.f, s3 = 0.f;
    if (CHK == 0) {
        for (int k = lane * 4; k < K; k += 128) {
            s0 += A[(size_t)row * lda + k + 0] * B[(size_t)col * ldb + k + 0];
            s1 += A[(size_t)row * lda + k + 1] * B[(size_t)col * ldb + k + 1];
            s2 += A[(size_t)row * lda + k + 2] * B[(size_t)col * ldb + k + 2];
            s3 += A[(size_t)row * lda + k + 3] * B[(size_t)col * ldb + k + 3];
        }
    } else {
        for (int k = lane * 4; k < K; k += 128) {
            s0 += A[(size_t)row * lda + k + 0] * B[(size_t)(k + 0) * ldb + col];
            s1 += A[(size_t)row * lda + k + 1] * B[(size_t)(k + 1) * ldb + col];
            s2 += A[(size_t)row * lda + k + 2] * B[(size_t)(k + 2) * ldb + col];
            s3 += A[(size_t)row * lda + k + 3] * B[(size_t)(k + 3) * ldb + col];
        }
    }
    float s = (s0 + s1) + (s2 + s3);
#pragma unroll
    for (int o = 16; o; o >>= 1) s += __shfl_xor_sync(0xFFFFFFFFu, s, o);
    if (lane == 0) {
        float ref = s + (bias ? bias[col] : 0.f);
        float got = Cc[(size_t)row * D + col];
        float tol = 0.02f * fabsf(ref) + 1e-3f;
        if (!(fabsf(got - ref) <= tol)) {
            if (CHK == 0) atomicExch(&d_flag0, 1);
            else          atomicExch(&d_flag1, 1);
        }
    }
}

// ---------------- f32x2 fallback GEMM (flag-gated) ----------------------------
template<int FM>
__global__ void __launch_bounds__(256) k_fp(const float* __restrict__ B, int ldb,
                                            const float* __restrict__ bias,
                                            float* __restrict__ outp) {
    if (((FM == 2) ? d_flag1 : d_flag0) == 0) return;
    const float* __restrict__ A = (FM == 0) ? d_pooled : (FM == 1) ? d_query
                                 : (FM == 2) ? d_AW : d_C1;
    float* __restrict__ Cout = (FM == 0) ? d_query : (FM == 1) ? d_base
                               : (FM == 2) ? d_C1 : outp;
    const int lda  = (FM == 2) ? NBUF : D;
    const int K    = (FM == 2) ? NBUF : D;
    const int Ntot = (FM == 1) ? NBUF : D;
    const int TRANSB = (FM == 2) ? 1 : 0;
    const float scale = (FM == 1) ? 0.022097086912079608f : 1.0f;

    __shared__ float As[32][64];
    __shared__ float Bs[32][128];
    const int tid = threadIdx.x, tx = tid & 15, ty = tid >> 4;
    const int n0 = blockIdx.x * 128;
    double acc[4][4];
#pragma unroll
    for (int i = 0; i < 4; i++)
#pragma unroll
        for (int j = 0; j < 4; j++) acc[i][j] = 0.0;

    for (int k0 = 0; k0 < K; k0 += 32) {
#pragma unroll
        for (int j = 0; j < 2; j++) {
            int idx = tid * 2 + j, m = idx >> 3, c4 = idx & 7;
            float4 v = *(const float4*)&A[(size_t)m * lda + k0 + c4 * 4];
            As[c4 * 4 + 0][m] = v.x; As[c4 * 4 + 1][m] = v.y;
            As[c4 * 4 + 2][m] = v.z; As[c4 * 4 + 3][m] = v.w;
        }
        if (!TRANSB) {
#pragma unroll
            for (int j = 0; j < 4; j++) {
                int idx = tid * 4 + j, n = idx >> 3, c4 = idx & 7;
                float4 v = *(const float4*)&B[(size_t)(n0 + n) * ldb + k0 + c4 * 4];
                Bs[c4 * 4 + 0][n] = v.x; Bs[c4 * 4 + 1][n] = v.y;
                Bs[c4 * 4 + 2][n] = v.z; Bs[c4 * 4 + 3][n] = v.w;
            }
        } else {
#pragma unroll
            for (int j = 0; j < 4; j++) {
                int idx = tid * 4 + j, kk = idx >> 5, n4 = idx & 31;
                *(float4*)&Bs[kk][n4 * 4] =
                    *(const float4*)&B[(size_t)(k0 + kk) * ldb + n0 + n4 * 4];
            }
        }
        __syncthreads();
#pragma unroll 8
        for (int kk = 0; kk < 32; kk++) {
            float4 av = *(const float4*)&As[kk][ty * 4];
            double2 b01 = *(const double2*)&Bs[kk][tx * 8];
            double2 b23 = *(const double2*)&Bs[kk][tx * 8 + 4];
            double a0 = pack_dup(av.x), a1 = pack_dup(av.y);
            double a2 = pack_dup(av.z), a3 = pack_dup(av.w);
            fma2(acc[0][0], a0, b01.x); fma2(acc[0][1], a0, b01.y);
            fma2(acc[0][2], a0, b23.x); fma2(acc[0][3], a0, b23.y);
            fma2(acc[1][0], a1, b01.x); fma2(acc[1][1], a1, b01.y);
            fma2(acc[1][2], a1, b23.x); fma2(acc[1][3], a1, b23.y);
            fma2(acc[2][0], a2, b01.x); fma2(acc[2][1], a2, b01.y);
            fma2(acc[2][2], a2, b23.x); fma2(acc[2][3], a2, b23.y);
            fma2(acc[3][0], a3, b01.x); fma2(acc[3][1], a3, b01.y);
            fma2(acc[3][2], a3, b23.x); fma2(acc[3][3], a3, b23.y);
        }
        __syncthreads();
    }
    float ws = d_wsum;
#pragma unroll
    for (int i = 0; i < 4; i++) {
        int row = ty * 4 + i;
        float o[8];
        unpack2(acc[i][0], o[0], o[1]); unpack2(acc[i][1], o[2], o[3]);
        unpack2(acc[i][2], o[4], o[5]); unpack2(acc[i][3], o[6], o[7]);
#pragma unroll
        for (int j = 0; j < 8; j++) {
            int col = n0 + tx * 8 + j;
            float c = o[j] * scale;
            if (FM == 3)       c = (ws > 0.f) ? c / fmaxf(ws, 1e-8f) + bias[col] : 0.f;
            else if (FM == 0)  c += bias[col];
            Cout[(size_t)row * Ntot + col] = c;
            if (FM == 0 || FM == 2) {  // refresh bf16 staging for next mma stage
                __nv_bfloat16 h, l; splitw(c, h, l);
                d_Ahi[(size_t)row * Ntot + col] = h;
                d_Alo[(size_t)row * Ntot + col] = l;
            }
        }
    }
}

// ---------------- valid_mask dtype detection + init ---------------------------
__global__ void k_detect(const void* vm) {
    __shared__ int mode;
    if (threadIdx.x == 0) {
        const float* fp = (const float*)vm;
        const int*   ip = (const int*)vm;
        bool isF = true, isI = true;
        for (int k = 0; k < 64; k++) {
            float f = fp[k];
            if (!(f == 0.0f || f == 1.0f)) isF = false;
            int v = ip[k];
            if (!(v == 0 || v == 1)) isI = false;
        }
        mode = isF ? 2 : (isI ? 1 : 0);
    }
    __syncthreads();
    int m = mode;
    const unsigned char* cp = (const unsigned char*)vm;
    const int*   ip = (const int*)vm;
    const float* fp = (const float*)vm;
    for (int n = threadIdx.x; n < NBUF; n += blockDim.x) {
        float v;
        if (m == 2)      v = (fp[n] != 0.0f) ? 1.f : 0.f;
        else if (m == 1) v = (ip[n] != 0)    ? 1.f : 0.f;
        else             v = (cp[n] != 0)    ? 1.f : 0.f;
        d_validf[n] = v;
    }
    if (threadIdx.x <= ROUNDS) d_active[threadIdx.x] = 0.f;
    if (threadIdx.x == 0) { d_wsum = 0.f; d_flag0 = 0; d_flag1 = 0; }
}

// ---------------- masked mean pool (writes fp32 + bf16 hi/lo) ------------------
__global__ void __launch_bounds__(256) k_pool(const float* __restrict__ qs,
                                              const float* __restrict__ mask) {
    int b = blockIdx.y;
    int d = blockIdx.x * 256 + threadIdx.x;
    __shared__ float sm[T];
    __shared__ float red[256];
    for (int t = threadIdx.x; t < T; t += 256) sm[t] = mask[b * T + t];
    __syncthreads();
    red[threadIdx.x] = sm[threadIdx.x] + sm[threadIdx.x + 256];
    __syncthreads();
    for (int off = 128; off > 0; off >>= 1) {
        if (threadIdx.x < off) red[threadIdx.x] += red[threadIdx.x + off];
        __syncthreads();
    }
    float msum = red[0];
    const float* base = qs + ((size_t)b * T) * D + d;
    float a0 = 0, a1 = 0, a2 = 0, a3 = 0;
#pragma unroll 2
    for (int t = 0; t < T; t += 8) {
        a0 += base[(size_t)(t + 0) * D] * sm[t + 0];
        a1 += base[(size_t)(t + 1) * D] * sm[t + 1];
        a2 += base[(size_t)(t + 2) * D] * sm[t + 2];
        a3 += base[(size_t)(t + 3) * D] * sm[t + 3];
        a0 += base[(size_t)(t + 4) * D] * sm[t + 4];
        a1 += base[(size_t)(t + 5) * D] * sm[t + 5];
        a2 += base[(size_t)(t + 6) * D] * sm[t + 6];
        a3 += base[(size_t)(t + 7) * D] * sm[t + 7];
    }
    float v = (a0 + a1 + a2 + a3) / (msum + 1e-8f);
    int idx = b * D + d;
    d_pooled[idx] = v;
    __nv_bfloat16 h, l; splitw(v, h, l);
    d_Ahi[idx] = h; d_Alo[idx] = l;
}

// ---------------- split-K reduces (producers also stage bf16) ------------------
__global__ void k_reduce_q(const float* __restrict__ bq) {
    int idx = blockIdx.x * 256 + threadIdx.x;
    if (idx >= Bb * D) return;
    float s = 0.f;
#pragma unroll
    for (int kz = 0; kz < 16; kz++) s += d_part[(size_t)kz * Bb * D + idx];
    float v = s + bq[idx & (D - 1)];
    d_query[idx] = v;
    __nv_bfloat16 h, l; splitw(v, h, l);
    d_Ahi[idx] = h; d_Alo[idx] = l;
}

__global__ void k_reduce_base() {
    int idx = blockIdx.x * 256 + threadIdx.x;
    float s = 0.f;
#pragma unroll
    for (int kz = 0; kz < 4; kz++) s += d_part[(size_t)kz * Bb * NBUF + idx];
    d_base[idx] = s * 0.022097086912079608f;
}

__global__ void k_reduce_c1() {
    int idx = blockIdx.x * 256 + threadIdx.x;
    if (idx >= Bb * D) return;
    float s = 0.f;
#pragma unroll
    for (int kz = 0; kz < 32; kz++) s += d_part[(size_t)kz * Bb * D + idx];
    d_C1[idx] = s;
    __nv_bfloat16 h, l; splitw(s, h, l);
    d_Ahi[idx] = h; d_Alo[idx] = l;
}

__global__ void k_reduce_out(const float* __restrict__ bc, float* __restrict__ out) {
    int idx = blockIdx.x * 256 + threadIdx.x;
    if (idx >= Bb * D) return;
    float ws = d_wsum;
    if (ws > 0.f) {
        float s = 0.f;
#pragma unroll
        for (int kz = 0; kz < 16; kz++) s += d_part[(size_t)kz * Bb * D + idx];
        out[idx] = s / fmaxf(ws, 1e-8f) + bc[idx & (D - 1)];
    } else {
        out[idx] = 0.f;
    }
}

// ---------------- persistent round-loop kernel (column-resident) ---------------
__device__ __forceinline__ void gridbar() {
    __syncthreads();
    if (threadIdx.x == 0) {
        __threadfence();
        unsigned g = atomicAdd(&d_bar_gen, 0u);
        if (atomicAdd(&d_bar_cnt, 1u) == GRIDB - 1u) {
            d_bar_cnt = 0u;
            __threadfence();
            atomicAdd(&d_bar_gen, 1u);
        } else {
            while (atomicAdd(&d_bar_gen, 0u) == g) { }
        }
        __threadfence();
    }
    __syncthreads();
}

__global__ void __launch_bounds__(256) k_rounds(const float* __restrict__ prio,
                                                const float* __restrict__ ages) {
    const int tid = threadIdx.x, blk = blockIdx.x;
    const int lane = tid & 31, wrp = tid >> 5;
    const int half = wrp >> 2;            // 0: rows 0..31, 1: rows 32..63
    const int col = blk * 128 + (tid & 127);
    const int blo = half * 32;
    __shared__ float spart[8][32];
    __shared__ float red[256];
    __shared__ float invs[64];
    const float DK = -0.105360515657826301f;  // ln(0.9)

    float wage = ages[col];
    float p    = prio[col];
    float vf   = d_validf[col];
    float gg, act;
    {
        float eff = p * __expf(wage * DK);
        act = vf / (1.f + __expf((0.5f - eff) * 10.f));
        gg = act * eff;
    }
    float aw_acc[32], e[32];
#pragma unroll
    for (int j = 0; j < 32; j++) aw_acc[j] = 0.f;

    // active(0): one thread per column contributes
    red[tid] = (tid < 128) ? act : 0.f; __syncthreads();
    for (int off = 128; off; off >>= 1) {
        if (tid < off) red[tid] += red[tid + off];
        __syncthreads();
    }
    if (tid == 0) atomicAdd(&d_active[0], red[0]);
    gridbar();

    float wsum = 0.f, rw = 1.f;
    for (int r = 0; r < ROUNDS; r++) {
        if (__ldcg(&d_active[r]) < 0.5f) break;
        wsum += rw;

        // ---- Phase 1: e in regs; per-warp row partials via shfl butterfly
#pragma unroll 8
        for (int j = 0; j < 32; j++)
            e[j] = vf * __expf(__ldg(&d_base[(size_t)(blo + j) * NBUF + col]) * gg);
#pragma unroll
        for (int j = 0; j < 32; j++) {
            float v = e[j];
#pragma unroll
            for (int off = 16; off; off >>= 1)
                v += __shfl_xor_sync(0xFFFFFFFFu, v, off);
            if (lane == j) spart[wrp][j] = v;
        }
        __syncthreads();
        if (tid < 64) {
            int hb = (tid >> 5) * 4, j = tid & 31;
            float t = spart[hb + 0][j] + spart[hb + 1][j]
                    + spart[hb + 2][j] + spart[hb + 3][j];
            __stcg(&d_rs_part[blk * Bb + tid], t);
        }
        gridbar();

        // ---- Phase 2: global rowsums -> invs
        {
            int rrow = tid & 63, grp = tid >> 6;
            float s = 0.f;
#pragma unroll 8
            for (int bi = 0; bi < 32; bi++)
                s += __ldcg(&d_rs_part[(size_t)(grp * 32 + bi) * Bb + rrow]);
            red[tid] = s; __syncthreads();
            if (tid < 64)
                invs[tid] = 1.f / (red[tid] + red[tid + 64] + red[tid + 128] + red[tid + 192]);
            __syncthreads();
        }
        // ---- aw accumulate + column sums
        float cs = 0.f;
#pragma unroll
        for (int j = 0; j < 32; j++) {
            float a = e[j] * invs[blo + j];
            aw_acc[j] += rw * a;
            cs += a;
        }
        __syncthreads();
        red[tid] = cs; __syncthreads();
        float cfull = red[tid & 127] + red[(tid & 127) + 128];
        wage += cfull * (1.f / 64.f);
        {
            float eff = p * __expf(wage * DK);
            act = vf / (1.f + __expf((0.5f - eff) * 10.f));
            gg = act * eff;
        }
        __syncthreads();
        red[tid] = (tid < 128) ? act : 0.f; __syncthreads();
        for (int off = 128; off; off >>= 1) {
            if (tid < off) red[tid] += red[tid + off];
            __syncthreads();
        }
        if (tid == 0) atomicAdd(&d_active[r + 1], red[0]);
        gridbar();
        rw *= 0.9f;
    }
    // final AW store: fp32 (for check/fallback) + bf16 hi/lo staging for mm2
#pragma unroll 8
    for (int j = 0; j < 32; j++) {
        size_t idx = (size_t)(blo + j) * NBUF + col;
        float v = aw_acc[j];
        d_AW[idx] = v;
        __nv_bfloat16 h, l; splitw(v, h, l);
        d_Ahi[idx] = h; d_Alo[idx] = l;
    }
    if (blk == 0 && tid == 0) d_wsum = wsum;
}

// ---------------- launch ------------------------------------------------------
extern "C" void kernel_launch(void* const* d_in, const int* in_sizes, int n_in,
                              void* d_out, int out_size) {
    const float* qs     = (const float*)d_in[0];
    const float* amask  = (const float*)d_in[1];
    const float* keys   = (const float*)d_in[2];
    const float* values = (const float*)d_in[3];
    const float* prio   = (const float*)d_in[4];
    const float* ages   = (const float*)d_in[5];
    const void*  vmask  = d_in[6];
    const float* Wq     = (const float*)d_in[7];
    const float* bq     = (const float*)d_in[8];
    const float* Wc     = (const float*)d_in[9];
    const float* bc     = (const float*)d_in[10];
    float* out = (float*)d_out;

    cudaFuncSetAttribute(k_mm<0>, cudaFuncAttributeMaxDynamicSharedMemorySize, SMEM_MM);
    cudaFuncSetAttribute(k_mm<1>, cudaFuncAttributeMaxDynamicSharedMemorySize, SMEM_MM);
    cudaFuncSetAttribute(k_mm<2>, cudaFuncAttributeMaxDynamicSharedMemorySize, SMEM_MM);
    cudaFuncSetAttribute(k_mm<3>, cudaFuncAttributeMaxDynamicSharedMemorySize, SMEM_MM);

    k_detect<<<1, 256>>>(vmask);
    k_pool<<<dim3(8, 64), 256>>>(qs, amask);

    // query = pooled @ Wq^T + bq  (mma split-K=16; checked; f32x2 fallback)
    k_mm<0><<<dim3(16, 16), 256, SMEM_MM>>>(Wq, D);
    k_reduce_q<<<(Bb * D + 255) / 256, 256>>>(bq);
    k_check<0><<<8, 256>>>(Wq, D, bq);
    k_fp<0><<<16, 256>>>(Wq, D, bq, (float*)0);

    // base = query @ keys^T * SC  (mma split-K=4; gated by flag0)
    k_mm<1><<<dim3(128, 4), 256, SMEM_MM>>>(keys, D);
    k_reduce_base<<<(Bb * NBUF) / 256, 256>>>();
    k_fp<1><<<128, 256>>>(keys, D, (const float*)0, (float*)0);

    k_rounds<<<GRIDB, 256>>>(prio, ages);

    // C1 = AW @ values  (mma split-K=32; checked; fallback)
    k_mm<2><<<dim3(16, 32), 256, SMEM_MM>>>(values, D);
    k_reduce_c1<<<(Bb * D + 255) / 256, 256>>>();
    k_check<1><<<1, 256>>>(values, D, (const float*)0);
    k_fp<2><<<16, 256>>>(values, D, (const float*)0, (float*)0);

    // out = (C1 @ Wc^T)/wsum + bc
    k_mm<3><<<dim3(16, 16), 256, SMEM_MM>>>(Wc, D);
    k_reduce_out<<<(Bb * D + 255) / 256, 256>>>(bc, out);
    k_fp<3><<<16, 256>>>(Wc, D, bc, out);
}

// round 16
// speedup vs baseline: 1.3024x; 1.1853x over previous
#include <cuda_runtime.h>
#include <cuda_bf16.h>
#include <math.h>
#include <stdint.h>

#define Bb      64
#define T       512
#define D       2048
#define NBUF    16384
#define ROUNDS  10
#define GRIDB   128
#define PAD     40
#define SMEM_MM (1536 * PAD)   // bytes: 2 bufs x (A hi/lo 64*PAD + B hi/lo 128*PAD) bf16

// ---------------- scratch (static device globals; no allocation) -------------
// RULE: device symbols are ONLY referenced inside __global__ code, never passed
// as launch arguments (host symbol address + GB300 ATS = silent host aliasing).
__device__ float d_pooled[Bb * D];
__device__ float d_query[Bb * D];
__device__ float d_base[Bb * NBUF];
__device__ float d_AW[Bb * NBUF];
__device__ __align__(16) __nv_bfloat16 d_Ahi[Bb * NBUF];  // staged A operand (hi)
__device__ __align__(16) __nv_bfloat16 d_Alo[Bb * NBUF];  // staged A operand (lo)
__device__ float d_validf[NBUF];
__device__ float d_rs_part[2 * GRIDB * Bb];  // [parity][block][row] rowsum partials
__device__ float d_act[2 * GRIDB];           // [parity][block] act partials
__device__ float d_C1[Bb * D];
__device__ float d_part[4 * Bb * NBUF];      // 16.8 MB split-K partials
__device__ float d_wsum;
__device__ int   d_flag0;
__device__ int   d_flag1;
__device__ unsigned d_bar_cnt;
__device__ unsigned d_bar_gen;

// ---------------- mma helpers -------------------------------------------------
__device__ __forceinline__ void mma16816(float* c, const uint32_t* a,
                                         uint32_t b0, uint32_t b1) {
    asm volatile("mma.sync.aligned.m16n8k16.row.col.f32.bf16.bf16.f32 "
                 "{%0,%1,%2,%3}, {%4,%5,%6,%7}, {%8,%9}, {%0,%1,%2,%3};"
                 : "+f"(c[0]), "+f"(c[1]), "+f"(c[2]), "+f"(c[3])
                 : "r"(a[0]), "r"(a[1]), "r"(a[2]), "r"(a[3]), "r"(b0), "r"(b1));
}
__device__ __forceinline__ uint32_t pack2(__nv_bfloat16 a, __nv_bfloat16 b) {
    return ((uint32_t)__bfloat16_as_ushort(b) << 16) | __bfloat16_as_ushort(a);
}
__device__ __forceinline__ void split4(float4 v, uint2& H, uint2& L) {
    __nv_bfloat16 hx = __float2bfloat16(v.x), hy = __float2bfloat16(v.y);
    __nv_bfloat16 hz = __float2bfloat16(v.z), hw = __float2bfloat16(v.w);
    __nv_bfloat16 lx = __float2bfloat16(v.x - __bfloat162float(hx));
    __nv_bfloat16 ly = __float2bfloat16(v.y - __bfloat162float(hy));
    __nv_bfloat16 lz = __float2bfloat16(v.z - __bfloat162float(hz));
    __nv_bfloat16 lw = __float2bfloat16(v.w - __bfloat162float(hw));
    H.x = pack2(hx, hy); H.y = pack2(hz, hw);
    L.x = pack2(lx, ly); L.y = pack2(lz, lw);
}
__device__ __forceinline__ void splitw(float v, __nv_bfloat16& h, __nv_bfloat16& l) {
    h = __float2bfloat16(v);
    l = __float2bfloat16(v - __bfloat162float(h));
}
__device__ __forceinline__ double pack_dup(float a) {
    double r; asm("mov.b64 %0, {%1, %1};" : "=d"(r) : "f"(a)); return r;
}
__device__ __forceinline__ void fma2(double& acc, double a, double b) {
    asm("fma.rn.f32x2 %0, %1, %2, %0;" : "+d"(acc) : "d"(a), "d"(b));
}
__device__ __forceinline__ void unpack2(double v, float& lo, float& hi) {
    asm("mov.b64 {%0, %1}, %2;" : "=f"(lo), "=f"(hi) : "d"(v));
}

// ---------------- MODE table ---------------------------------------------------
// A comes from d_Ahi/d_Alo (pre-converted by the producer kernel of that stage).
template<int MODE> struct MM {
    static const int TRANSB = (MODE == 2) ? 1 : 0;
    static const int LDA    = (MODE == 2) ? NBUF : D;
    static const int NTOT   = (MODE == 1) ? NBUF : D;
    static const int KSL    = (MODE == 0 || MODE == 3) ? 128 : 512;
};

// ---------------- split-precision bf16 mma GEMM (R13 config) -------------------
template<int MODE>
__global__ void __launch_bounds__(256) k_mm(const float* __restrict__ B, int ldb) {
    const int TRANSB = MM<MODE>::TRANSB;
    const int lda = MM<MODE>::LDA, Ntot = MM<MODE>::NTOT, Kslice = MM<MODE>::KSL;
    extern __shared__ __nv_bfloat16 sm_[];
    __nv_bfloat16* sAhi = sm_;                                   // [2][64*PAD]
    __nv_bfloat16* sAlo = sm_ + 2 * 64 * PAD;
    __nv_bfloat16* sBhi = sm_ + 4 * 64 * PAD;                    // [2][128*PAD]
    __nv_bfloat16* sBlo = sm_ + 4 * 64 * PAD + 2 * 128 * PAD;

    const int tid = threadIdx.x, lane = tid & 31, w = tid >> 5;
    const int wm = w >> 2, wn = w & 3;
    const int g = lane >> 2, t2 = (lane & 3) * 2;
    const int n0 = blockIdx.x * 128;
    const int kbase = blockIdx.y * Kslice;
    const int nct = Kslice >> 5;
    const int am = tid >> 2, ac8 = (tid & 3) * 8;   // A tile: 64 rows x 32 cols / 8

    float acc[2][4][4];
#pragma unroll
    for (int f = 0; f < 2; f++)
#pragma unroll
        for (int q = 0; q < 4; q++)
#pragma unroll
            for (int i = 0; i < 4; i++) acc[f][q][i] = 0.f;

    uint4 rahi, ralo;
    float4 rb[4];
    auto loadT = [&](int c) {
        const int k0 = kbase + c * 32;
        rahi = *(const uint4*)&d_Ahi[(size_t)am * lda + k0 + ac8];
        ralo = *(const uint4*)&d_Alo[(size_t)am * lda + k0 + ac8];
        if (!TRANSB) {
#pragma unroll
            for (int j = 0; j < 4; j++) {
                int idx = tid * 4 + j, r = idx >> 3, c4 = (idx & 7) * 4;
                rb[j] = *(const float4*)&B[(size_t)(n0 + r) * ldb + k0 + c4];
            }
        } else {
            int cc = tid & 127, rbse = (tid >> 7) * 4;
#pragma unroll
            for (int j = 0; j < 4; j++) {
                int rr = rbse + j * 8;
                rb[j].x = B[(size_t)(k0 + rr + 0) * ldb + n0 + cc];
                rb[j].y = B[(size_t)(k0 + rr + 1) * ldb + n0 + cc];
                rb[j].z = B[(size_t)(k0 + rr + 2) * ldb + n0 + cc];
                rb[j].w = B[(size_t)(k0 + rr + 3) * ldb + n0 + cc];
            }
        }
    };
    auto storeT = [&](int buf) {
        int abase = buf * 64 * PAD, bbase = buf * 128 * PAD;
        *(uint4*)&sAhi[abase + am * PAD + ac8] = rahi;
        *(uint4*)&sAlo[abase + am * PAD + ac8] = ralo;
        if (!TRANSB) {
#pragma unroll
            for (int j = 0; j < 4; j++) {
                int idx = tid * 4 + j, r = idx >> 3, c4 = (idx & 7) * 4;
                uint2 H, L; split4(rb[j], H, L);
                *(uint2*)&sBhi[bbase + r * PAD + c4] = H;
                *(uint2*)&sBlo[bbase + r * PAD + c4] = L;
            }
        } else {
            int cc = tid & 127, rbse = (tid >> 7) * 4;
#pragma unroll
            for (int j = 0; j < 4; j++) {
                int rr = rbse + j * 8;
                uint2 H, L; split4(rb[j], H, L);
                *(uint2*)&sBhi[bbase + cc * PAD + rr] = H;
                *(uint2*)&sBlo[bbase + cc * PAD + rr] = L;
            }
        }
    };

    loadT(0);
    storeT(0);
    __syncthreads();
    int buf = 0;
    for (int c = 0; c < nct; c++) {
        bool more = (c + 1 < nct);
        if (more) loadT(c + 1);
        const int abase = buf * 64 * PAD, bbase = buf * 128 * PAD;
#pragma unroll
        for (int ks = 0; ks < 32; ks += 16) {
            const int cA = ks + t2;
            uint32_t ahi[2][4], alo[2][4];
#pragma unroll
            for (int f = 0; f < 2; f++) {
                int rabs = abase + (wm * 32 + f * 16 + g) * PAD;
                ahi[f][0] = *(const uint32_t*)&sAhi[rabs + cA];
                ahi[f][1] = *(const uint32_t*)&sAhi[rabs + 8 * PAD + cA];
                ahi[f][2] = *(const uint32_t*)&sAhi[rabs + cA + 8];
                ahi[f][3] = *(const uint32_t*)&sAhi[rabs + 8 * PAD + cA + 8];
                alo[f][0] = *(const uint32_t*)&sAlo[rabs + cA];
                alo[f][1] = *(const uint32_t*)&sAlo[rabs + 8 * PAD + cA];
                alo[f][2] = *(const uint32_t*)&sAlo[rabs + cA + 8];
                alo[f][3] = *(const uint32_t*)&sAlo[rabs + 8 * PAD + cA + 8];
            }
#pragma unroll
            for (int nb = 0; nb < 4; nb++) {
                int ncb = bbase + (wn * 32 + nb * 8 + g) * PAD;
                uint32_t bh0 = *(const uint32_t*)&sBhi[ncb + cA];
                uint32_t bh1 = *(const uint32_t*)&sBhi[ncb + cA + 8];
                uint32_t bl0 = *(const uint32_t*)&sBlo[ncb + cA];
                uint32_t bl1 = *(const uint32_t*)&sBlo[ncb + cA + 8];
#pragma unroll
                for (int f = 0; f < 2; f++) {
                    mma16816(acc[f][nb], ahi[f], bh0, bh1);
                    mma16816(acc[f][nb], ahi[f], bl0, bl1);
                    mma16816(acc[f][nb], alo[f], bh0, bh1);
                }
            }
        }
        if (more) storeT(buf ^ 1);
        __syncthreads();
        buf ^= 1;
    }

    float* Cp = d_part + (size_t)blockIdx.y * 64 * Ntot;
    int r0 = wm * 32 + g;
#pragma unroll
    for (int f = 0; f < 2; f++)
#pragma unroll
        for (int nb = 0; nb < 4; nb++) {
            int rr = r0 + f * 16;
            int col = n0 + wn * 32 + nb * 8 + t2;
            *(float2*)&Cp[(size_t)rr * Ntot + col] =
                make_float2(acc[f][nb][0], acc[f][nb][1]);
            *(float2*)&Cp[(size_t)(rr + 8) * Ntot + col] =
                make_float2(acc[f][nb][2], acc[f][nb][3]);
        }
}

// ---------------- fp32 sample checks ------------------------------------------
__global__ void k_check0(const float* __restrict__ B, int ldb,
                         const float* __restrict__ bias) {
    int gw = (blockIdx.x * blockDim.x + threadIdx.x) >> 5;
    int lane = threadIdx.x & 31;
    int row = (gw * 37) & 63;
    int col = (int)((gw * 2654435761u) % (unsigned)D);
    float s0 = 0.f, s1 = 0.f, s2 = 0.f, s3 = 0.f;
    for (int k = lane * 4; k < D; k += 128) {
        s0 += d_pooled[(size_t)row * D + k + 0] * B[(size_t)col * ldb + k + 0];
        s1 += d_pooled[(size_t)row * D + k + 1] * B[(size_t)col * ldb + k + 1];
        s2 += d_pooled[(size_t)row * D + k + 2] * B[(size_t)col * ldb + k + 2];
        s3 += d_pooled[(size_t)row * D + k + 3] * B[(size_t)col * ldb + k + 3];
    }
    float s = (s0 + s1) + (s2 + s3);
#pragma unroll
    for (int o = 16; o; o >>= 1) s += __shfl_xor_sync(0xFFFFFFFFu, s, o);
    if (lane == 0) {
        float ref = s + bias[col];
        float got = d_query[(size_t)row * D + col];
        float tol = 0.02f * fabsf(ref) + 1e-3f;
        if (!(fabsf(got - ref) <= tol)) atomicExch(&d_flag0, 1);
    }
}

// block-per-sample: 8 blocks x 256 threads, k-strided for MLP
__global__ void __launch_bounds__(256) k_check1(const float* __restrict__ B, int ldb) {
    __shared__ float red[256];
    int tid = threadIdx.x, samp = blockIdx.x;
    int row = (samp * 37) & 63;
    int col = (int)((samp * 2654435761u) % (unsigned)D);
    float s = 0.f;
    for (int k = tid; k < NBUF; k += 256)
        s += d_AW[(size_t)row * NBUF + k] * B[(size_t)k * ldb + col];
    red[tid] = s; __syncthreads();
    for (int off = 128; off; off >>= 1) {
        if (tid < off) red[tid] += red[tid + off];
        __syncthreads();
    }
    if (tid == 0) {
        float ref = red[0];
        float got = d_C1[(size_t)row * D + col];
        float tol = 0.02f * fabsf(ref) + 1e-3f;
        if (!(fabsf(got - ref) <= tol)) atomicExch(&d_flag1, 1);
    }
}

// ---------------- f32x2 fallback GEMM (flag-gated) ----------------------------
template<int FM>
__global__ void __launch_bounds__(256) k_fp(const float* __restrict__ B, int ldb,
                                            const float* __restrict__ bias,
                                            float* __restrict__ outp) {
    if (((FM == 2) ? d_flag1 : d_flag0) == 0) return;
    const float* __restrict__ A = (FM == 0) ? d_pooled : (FM == 1) ? d_query
                                 : (FM == 2) ? d_AW : d_C1;
    float* __restrict__ Cout = (FM == 0) ? d_query : (FM == 1) ? d_base
                               : (FM == 2) ? d_C1 : outp;
    const int lda  = (FM == 2) ? NBUF : D;
    const int K    = (FM == 2) ? NBUF : D;
    const int Ntot = (FM == 1) ? NBUF : D;
    const int TRANSB = (FM == 2) ? 1 : 0;
    const float scale = (FM == 1) ? 0.022097086912079608f : 1.0f;

    __shared__ float As[32][64];
    __shared__ float Bs[32][128];
    const int tid = threadIdx.x, tx = tid & 15, ty = tid >> 4;
    const int n0 = blockIdx.x * 128;
    double acc[4][4];
#pragma unroll
    for (int i = 0; i < 4; i++)
#pragma unroll
        for (int j = 0; j < 4; j++) acc[i][j] = 0.0;

    for (int k0 = 0; k0 < K; k0 += 32) {
#pragma unroll
        for (int j = 0; j < 2; j++) {
            int idx = tid * 2 + j, m = idx >> 3, c4 = idx & 7;
            float4 v = *(const float4*)&A[(size_t)m * lda + k0 + c4 * 4];
            As[c4 * 4 + 0][m] = v.x; As[c4 * 4 + 1][m] = v.y;
            As[c4 * 4 + 2][m] = v.z; As[c4 * 4 + 3][m] = v.w;
        }
        if (!TRANSB) {
#pragma unroll
            for (int j = 0; j < 4; j++) {
                int idx = tid * 4 + j, n = idx >> 3, c4 = idx & 7;
                float4 v = *(const float4*)&B[(size_t)(n0 + n) * ldb + k0 + c4 * 4];
                Bs[c4 * 4 + 0][n] = v.x; Bs[c4 * 4 + 1][n] = v.y;
                Bs[c4 * 4 + 2][n] = v.z; Bs[c4 * 4 + 3][n] = v.w;
            }
        } else {
#pragma unroll
            for (int j = 0; j < 4; j++) {
                int idx = tid * 4 + j, kk = idx >> 5, n4 = idx & 31;
                *(float4*)&Bs[kk][n4 * 4] =
                    *(const float4*)&B[(size_t)(k0 + kk) * ldb + n0 + n4 * 4];
            }
        }
        __syncthreads();
#pragma unroll 8
        for (int kk = 0; kk < 32; kk++) {
            float4 av = *(const float4*)&As[kk][ty * 4];
            double2 b01 = *(const double2*)&Bs[kk][tx * 8];
            double2 b23 = *(const double2*)&Bs[kk][tx * 8 + 4];
            double a0 = pack_dup(av.x), a1 = pack_dup(av.y);
            double a2 = pack_dup(av.z), a3 = pack_dup(av.w);
            fma2(acc[0][0], a0, b01.x); fma2(acc[0][1], a0, b01.y);
            fma2(acc[0][2], a0, b23.x); fma2(acc[0][3], a0, b23.y);
            fma2(acc[1][0], a1, b01.x); fma2(acc[1][1], a1, b01.y);
            fma2(acc[1][2], a1, b23.x); fma2(acc[1][3], a1, b23.y);
            fma2(acc[2][0], a2, b01.x); fma2(acc[2][1], a2, b01.y);
            fma2(acc[2][2], a2, b23.x); fma2(acc[2][3], a2, b23.y);
            fma2(acc[3][0], a3, b01.x); fma2(acc[3][1], a3, b01.y);
            fma2(acc[3][2], a3, b23.x); fma2(acc[3][3], a3, b23.y);
        }
        __syncthreads();
    }
    float ws = d_wsum;
#pragma unroll
    for (int i = 0; i < 4; i++) {
        int row = ty * 4 + i;
        float o[8];
        unpack2(acc[i][0], o[0], o[1]); unpack2(acc[i][1], o[2], o[3]);
        unpack2(acc[i][2], o[4], o[5]); unpack2(acc[i][3], o[6], o[7]);
#pragma unroll
        for (int j = 0; j < 8; j++) {
            int col = n0 + tx * 8 + j;
            float c = o[j] * scale;
            if (FM == 3)       c = (ws > 0.f) ? c / fmaxf(ws, 1e-8f) + bias[col] : 0.f;
            else if (FM == 0)  c += bias[col];
            Cout[(size_t)row * Ntot + col] = c;
            if (FM == 0 || FM == 2) {
                __nv_bfloat16 h, l; splitw(c, h, l);
                d_Ahi[(size_t)row * Ntot + col] = h;
                d_Alo[(size_t)row * Ntot + col] = l;
            }
        }
    }
}

// ---------------- valid_mask dtype detection + init ---------------------------
__global__ void k_detect(const void* vm) {
    __shared__ int mode;
    if (threadIdx.x == 0) {
        const float* fp = (const float*)vm;
        const int*   ip = (const int*)vm;
        bool isF = true, isI = true;
        for (int k = 0; k < 64; k++) {
            float f = fp[k];
            if (!(f == 0.0f || f == 1.0f)) isF = false;
            int v = ip[k];
            if (!(v == 0 || v == 1)) isI = false;
        }
        mode = isF ? 2 : (isI ? 1 : 0);
    }
    __syncthreads();
    int m = mode;
    const unsigned char* cp = (const unsigned char*)vm;
    const int*   ip = (const int*)vm;
    const float* fp = (const float*)vm;
    for (int n = threadIdx.x; n < NBUF; n += blockDim.x) {
        float v;
        if (m == 2)      v = (fp[n] != 0.0f) ? 1.f : 0.f;
        else if (m == 1) v = (ip[n] != 0)    ? 1.f : 0.f;
        else             v = (cp[n] != 0)    ? 1.f : 0.f;
        d_validf[n] = v;
    }
    if (threadIdx.x == 0) { d_wsum = 0.f; d_flag0 = 0; d_flag1 = 0; }
}

// ---------------- masked mean pool (float4, writes fp32 + bf16 hi/lo) ----------
__global__ void __launch_bounds__(256) k_pool(const float* __restrict__ qs,
                                              const float* __restrict__ mask) {
    int b = blockIdx.y;
    int d4 = (blockIdx.x * 256 + threadIdx.x) * 4;
    __shared__ float sm[T];
    __shared__ float red[256];
    for (int t = threadIdx.x; t < T; t += 256) sm[t] = mask[b * T + t];
    __syncthreads();
    red[threadIdx.x] = sm[threadIdx.x] + sm[threadIdx.x + 256];
    __syncthreads();
    for (int off = 128; off > 0; off >>= 1) {
        if (threadIdx.x < off) red[threadIdx.x] += red[threadIdx.x + off];
        __syncthreads();
    }
    float msum = red[0];
    const float* base = qs + ((size_t)b * T) * D + d4;
    float4 a0 = make_float4(0, 0, 0, 0), a1 = make_float4(0, 0, 0, 0);
    float4 a2 = make_float4(0, 0, 0, 0), a3 = make_float4(0, 0, 0, 0);
#pragma unroll 2
    for (int t = 0; t < T; t += 4) {
        float4 v0 = *(const float4*)&base[(size_t)(t + 0) * D];
        float4 v1 = *(const float4*)&base[(size_t)(t + 1) * D];
        float4 v2 = *(const float4*)&base[(size_t)(t + 2) * D];
        float4 v3 = *(const float4*)&base[(size_t)(t + 3) * D];
        float m0 = sm[t + 0], m1 = sm[t + 1], m2 = sm[t + 2], m3 = sm[t + 3];
        a0.x += v0.x * m0; a0.y += v0.y * m0; a0.z += v0.z * m0; a0.w += v0.w * m0;
        a1.x += v1.x * m1; a1.y += v1.y * m1; a1.z += v1.z * m1; a1.w += v1.w * m1;
        a2.x += v2.x * m2; a2.y += v2.y * m2; a2.z += v2.z * m2; a2.w += v2.w * m2;
        a3.x += v3.x * m3; a3.y += v3.y * m3; a3.z += v3.z * m3; a3.w += v3.w * m3;
    }
    float inv = 1.f / (msum + 1e-8f);
    float4 r;
    r.x = (a0.x + a1.x + a2.x + a3.x) * inv;
    r.y = (a0.y + a1.y + a2.y + a3.y) * inv;
    r.z = (a0.z + a1.z + a2.z + a3.z) * inv;
    r.w = (a0.w + a1.w + a2.w + a3.w) * inv;
    size_t idx = (size_t)b * D + d4;
    *(float4*)&d_pooled[idx] = r;
    uint2 H, L; split4(r, H, L);
    *(uint2*)&d_Ahi[idx] = H;
    *(uint2*)&d_Alo[idx] = L;
}

// ---------------- split-K reduces (producers also stage bf16) ------------------
__global__ void k_reduce_q(const float* __restrict__ bq) {
    int idx = blockIdx.x * 256 + threadIdx.x;
    if (idx >= Bb * D) return;
    float s = 0.f;
#pragma unroll
    for (int kz = 0; kz < 16; kz++) s += d_part[(size_t)kz * Bb * D + idx];
    float v = s + bq[idx & (D - 1)];
    d_query[idx] = v;
    __nv_bfloat16 h, l; splitw(v, h, l);
    d_Ahi[idx] = h; d_Alo[idx] = l;
}

__global__ void k_reduce_base() {
    int idx = blockIdx.x * 256 + threadIdx.x;
    float s = 0.f;
#pragma unroll
    for (int kz = 0; kz < 4; kz++) s += d_part[(size_t)kz * Bb * NBUF + idx];
    d_base[idx] = s * 0.022097086912079608f;
}

__global__ void k_reduce_c1() {
    int idx = blockIdx.x * 256 + threadIdx.x;
    if (idx >= Bb * D) return;
    float s = 0.f;
#pragma unroll
    for (int kz = 0; kz < 32; kz++) s += d_part[(size_t)kz * Bb * D + idx];
    d_C1[idx] = s;
    __nv_bfloat16 h, l; splitw(s, h, l);
    d_Ahi[idx] = h; d_Alo[idx] = l;
}

__global__ void k_reduce_out(const float* __restrict__ bc, float* __restrict__ out) {
    int idx = blockIdx.x * 256 + threadIdx.x;
    if (idx >= Bb * D) return;
    float ws = d_wsum;
    if (ws > 0.f) {
        float s = 0.f;
#pragma unroll
        for (int kz = 0; kz < 16; kz++) s += d_part[(size_t)kz * Bb * D + idx];
        out[idx] = s / fmaxf(ws, 1e-8f) + bc[idx & (D - 1)];
    } else {
        out[idx] = 0.f;
    }
}

// ---------------- persistent round loop: ONE gridbar per round ------------------
__device__ __forceinline__ void gridbar() {
    __syncthreads();
    if (threadIdx.x == 0) {
        __threadfence();
        unsigned g = atomicAdd(&d_bar_gen, 0u);
        if (atomicAdd(&d_bar_cnt, 1u) == GRIDB - 1u) {
            d_bar_cnt = 0u;
            __threadfence();
            atomicAdd(&d_bar_gen, 1u);
        } else {
            while (atomicAdd(&d_bar_gen, 0u) == g) { }
        }
        __threadfence();
    }
    __syncthreads();
}

__global__ void __launch_bounds__(256) k_rounds(const float* __restrict__ prio,
                                                const float* __restrict__ ages) {
    const int tid = threadIdx.x, blk = blockIdx.x;
    const int lane = tid & 31, wrp = tid >> 5;
    const int half = wrp >> 2;            // 0: rows 0..31, 1: rows 32..63
    const int col = blk * 128 + (tid & 127);
    const int blo = half * 32;
    __shared__ float spart[8][32];
    __shared__ float red[256];
    __shared__ float invs[64];
    const float DK = -0.105360515657826301f;  // ln(0.9)

    float wage = ages[col];
    float p    = prio[col];
    float vf   = d_validf[col];
    float gg, act;
    {
        float eff = p * __expf(wage * DK);
        act = vf / (1.f + __expf((0.5f - eff) * 10.f));
        gg = act * eff;
    }
    float aw_acc[32], e[32];
#pragma unroll
    for (int j = 0; j < 32; j++) aw_acc[j] = 0.f;

    // helper-free prologue: act partial(0) -> d_act[0], e(0) + rs_part[0]
    red[tid] = (tid < 128) ? act : 0.f; __syncthreads();
    for (int off = 128; off; off >>= 1) {
        if (tid < off) red[tid] += red[tid + off];
        __syncthreads();
    }
    if (tid == 0) __stcg(&d_act[blk], red[0]);
    __syncthreads();
#pragma unroll 8
    for (int j = 0; j < 32; j++)
        e[j] = vf * __expf(__ldg(&d_base[(size_t)(blo + j) * NBUF + col]) * gg);
#pragma unroll
    for (int j = 0; j < 32; j++) {
        float v = e[j];
#pragma unroll
        for (int off = 16; off; off >>= 1)
            v += __shfl_xor_sync(0xFFFFFFFFu, v, off);
        if (lane == j) spart[wrp][j] = v;
    }
    __syncthreads();
    if (tid < 64) {
        int hb = (tid >> 5) * 4, j = tid & 31;
        float t = spart[hb + 0][j] + spart[hb + 1][j]
                + spart[hb + 2][j] + spart[hb + 3][j];
        __stcg(&d_rs_part[blk * Bb + tid], t);
    }
    gridbar();

    float wsum = 0.f, rw = 1.f;
    for (int r = 0; r < ROUNDS; r++) {
        const int par = r & 1;
        // ---- activeSum from d_act[par]
        red[tid] = (tid < GRIDB) ? __ldcg(&d_act[par * GRIDB + tid]) : 0.f;
        __syncthreads();
        for (int off = 128; off; off >>= 1) {
            if (tid < off) red[tid] += red[tid + off];
            __syncthreads();
        }
        float activeSum = red[0];
        __syncthreads();
        if (activeSum < 0.5f) break;
        wsum += rw;

        // ---- global rowsums from rs_part[par] -> invs
        {
            int rrow = tid & 63, grp = tid >> 6;
            float s = 0.f;
#pragma unroll 8
            for (int bi = 0; bi < 32; bi++)
                s += __ldcg(&d_rs_part[(size_t)par * GRIDB * Bb
                                       + (size_t)(grp * 32 + bi) * Bb + rrow]);
            red[tid] = s; __syncthreads();
            if (tid < 64)
                invs[tid] = 1.f / (red[tid] + red[tid + 64] + red[tid + 128] + red[tid + 192]);
            __syncthreads();
        }
        // ---- aw accumulate + column sums (uses e(r) already in regs)
        float cs = 0.f;
#pragma unroll
        for (int j = 0; j < 32; j++) {
            float a = e[j] * invs[blo + j];
            aw_acc[j] += rw * a;
            cs += a;
        }
        __syncthreads();
        red[tid] = cs; __syncthreads();
        float cfull = red[tid & 127] + red[(tid & 127) + 128];
        wage += cfull * (1.f / 64.f);
        {
            float eff = p * __expf(wage * DK);
            act = vf / (1.f + __expf((0.5f - eff) * 10.f));
            gg = act * eff;
        }
        rw *= 0.9f;

        if (r + 1 < ROUNDS) {
            // ---- speculative: act partial(r+1) -> d_act[par^1]
            __syncthreads();
            red[tid] = (tid < 128) ? act : 0.f; __syncthreads();
            for (int off = 128; off; off >>= 1) {
                if (tid < off) red[tid] += red[tid + off];
                __syncthreads();
            }
            if (tid == 0) __stcg(&d_act[(par ^ 1) * GRIDB + blk], red[0]);
            // ---- speculative: e(r+1) + rs_part[par^1]
#pragma unroll 8
            for (int j = 0; j < 32; j++)
                e[j] = vf * __expf(__ldg(&d_base[(size_t)(blo + j) * NBUF + col]) * gg);
#pragma unroll
            for (int j = 0; j < 32; j++) {
                float v = e[j];
#pragma unroll
                for (int off = 16; off; off >>= 1)
                    v += __shfl_xor_sync(0xFFFFFFFFu, v, off);
                if (lane == j) spart[wrp][j] = v;
            }
            __syncthreads();
            if (tid < 64) {
                int hb = (tid >> 5) * 4, j = tid & 31;
                float t = spart[hb + 0][j] + spart[hb + 1][j]
                        + spart[hb + 2][j] + spart[hb + 3][j];
                __stcg(&d_rs_part[(size_t)(par ^ 1) * GRIDB * Bb + blk * Bb + tid], t);
            }
            gridbar();
        }
    }
    // final AW store: fp32 + bf16 hi/lo staging for mm2
#pragma unroll 8
    for (int j = 0; j < 32; j++) {
        size_t idx = (size_t)(blo + j) * NBUF + col;
        float v = aw_acc[j];
        d_AW[idx] = v;
        __nv_bfloat16 h, l; splitw(v, h, l);
        d_Ahi[idx] = h; d_Alo[idx] = l;
    }
    if (blk == 0 && tid == 0) d_wsum = wsum;
}

// ---------------- launch ------------------------------------------------------
extern "C" void kernel_launch(void* const* d_in, const int* in_sizes, int n_in,
                              void* d_out, int out_size) {
    const float* qs     = (const float*)d_in[0];
    const float* amask  = (const float*)d_in[1];
    const float* keys   = (const float*)d_in[2];
    const float* values = (const float*)d_in[3];
    const float* prio   = (const float*)d_in[4];
    const float* ages   = (const float*)d_in[5];
    const void*  vmask  = d_in[6];
    const float* Wq     = (const float*)d_in[7];
    const float* bq     = (const float*)d_in[8];
    const float* Wc     = (const float*)d_in[9];
    const float* bc     = (const float*)d_in[10];
    float* out = (float*)d_out;

    cudaFuncSetAttribute(k_mm<0>, cudaFuncAttributeMaxDynamicSharedMemorySize, SMEM_MM);
    cudaFuncSetAttribute(k_mm<1>, cudaFuncAttributeMaxDynamicSharedMemorySize, SMEM_MM);
    cudaFuncSetAttribute(k_mm<2>, cudaFuncAttributeMaxDynamicSharedMemorySize, SMEM_MM);
    cudaFuncSetAttribute(k_mm<3>, cudaFuncAttributeMaxDynamicSharedMemorySize, SMEM_MM);

    k_detect<<<1, 256>>>(vmask);
    k_pool<<<dim3(2, 64), 256>>>(qs, amask);

    // query = pooled @ Wq^T + bq  (mma split-K=16; checked; f32x2 fallback)
    k_mm<0><<<dim3(16, 16), 256, SMEM_MM>>>(Wq, D);
    k_reduce_q<<<(Bb * D + 255) / 256, 256>>>(bq);
    k_check0<<<8, 256>>>(Wq, D, bq);
    k_fp<0><<<16, 256>>>(Wq, D, bq, (float*)0);

    // base = query @ keys^T * SC  (mma split-K=4; gated by flag0)
    k_mm<1><<<dim3(128, 4), 256, SMEM_MM>>>(keys, D);
    k_reduce_base<<<(Bb * NBUF) / 256, 256>>>();
    k_fp<1><<<128, 256>>>(keys, D, (const float*)0, (float*)0);

    k_rounds<<<GRIDB, 256>>>(prio, ages);

    // C1 = AW @ values  (mma split-K=32; checked; fallback)
    k_mm<2><<<dim3(16, 32), 256, SMEM_MM>>>(values, D);
    k_reduce_c1<<<(Bb * D + 255) / 256, 256>>>();
    k_check1<<<8, 256>>>(values, D);
    k_fp<2><<<16, 256>>>(values, D, (const float*)0, (float*)0);

    // out = (C1 @ Wc^T)/wsum + bc
    k_mm<3><<<dim3(16, 16), 256, SMEM_MM>>>(Wc, D);
    k_reduce_out<<<(Bb * D + 255) / 256, 256>>>(bc, out);
    k_fp<3><<<16, 256>>>(Wc, D, bc, out);
}